// round 9
// baseline (speedup 1.0000x reference)
#include <cuda_runtime.h>

// Problem shapes (fixed for this dataset entry)
#define B_   4
#define Q_   128
#define N_   50000
#define C_   20
#define BQ_  (B_ * Q_)          // 512
#define BN_  (B_ * N_)          // 200000
#define NV_  (N_ / 4)           // 12500 float4 per row
#define S_   10                 // chunks per row
#define CHUNK_ (NV_ / S_)       // 1250 float4 per chunk

#define MIN_PTS_NUM  50
#define MIN_INST_CLS 4

// Output layout (fp32 concatenation, matching reference return order)
#define OFF_SCORES ((size_t)BQ_ * N_)            // 25,600,000
#define OFF_VALID  (OFF_SCORES + BQ_)
#define OFF_CLS    (OFF_VALID + BQ_)
#define OFF_GID    (OFF_CLS + BQ_)

// Scratch (no device allocation -> __device__ globals). Written by plain
// overwriting stores every invocation -> idempotent across graph replays,
// no reset, no atomics, no fences.
__device__ int   g_part_cnt[BQ_][S_];
__device__ float g_part_sum[BQ_][S_];

// Inline per-row argmax over C=20 class logits. Matches jnp.argmax first-max.
__device__ __forceinline__ int row_argmax(const float* __restrict__ p)
{
    float best = __ldg(&p[0]);
    int bi = 0;
    #pragma unroll
    for (int c = 1; c < C_; c++) {
        float v = __ldg(&p[c]);
        if (v > best) { best = v; bi = c; }
    }
    return bi;
}

// ---------------------------------------------------------------------------
// Kernel 1: grid (S_, BQ_). One block per 1250-float4 chunk of one (b,q) row.
// __launch_bounds__(256, 6): keeps regs <= 40 -> 6 blocks/SM.
// Also absorbs the fg_idxs -> global_ids float convert (first 782 flattened
// blocks, one element/thread) -- free under the DRAM-bound main stream.
// cls<4 rows are invalid regardless of count -> stream zeros, no logit read.
// Otherwise: sel = (logit>0) & (seg==cls)  [sigmoid(x)>0.5 <=> x>0 -> no
// MUFU for selection]; write mask (streaming), block-reduce (count, sigmoid
// sum over selected), plain-store partials into the per-(row,chunk) slot.
// ---------------------------------------------------------------------------
__global__ __launch_bounds__(256, 6)
void mask_chunk_kernel(const float* __restrict__ mask_logits,
                       const float* __restrict__ cls_logits,
                       const int* __restrict__ seg_pred,
                       const int* __restrict__ fg_idxs,
                       float* __restrict__ out_masks,
                       float* __restrict__ out_gid)
{
    const int chunk = blockIdx.x;
    const int bq    = blockIdx.y;

    // Folded gid convert: flattened block id, one element per thread.
    {
        int gi = (bq * S_ + chunk) * 256 + threadIdx.x;
        if (gi < BN_) out_gid[gi] = (float)__ldg(&fg_idxs[gi]);
    }

    const int b   = bq >> 7;              // / Q_
    const int cls = row_argmax(cls_logits + bq * C_);
    const size_t base = (size_t)bq * NV_ + (size_t)chunk * CHUNK_;

    float4* __restrict__ om = reinterpret_cast<float4*>(out_masks) + base;

    if (cls < MIN_INST_CLS) {
        const float4 z = make_float4(0.f, 0.f, 0.f, 0.f);
        #pragma unroll
        for (int k = 0; k < 5; k++) {
            int i = threadIdx.x + k * 256;
            if (i < CHUNK_) __stcs(&om[i], z);
        }
        if (threadIdx.x == 0) {           // still publish partials (zero)
            g_part_cnt[bq][chunk] = 0;
            g_part_sum[bq][chunk] = 0.f;
        }
        return;
    }

    const float4* __restrict__ ml = reinterpret_cast<const float4*>(mask_logits) + base;
    const int4*   __restrict__ sp = reinterpret_cast<const int4*>(seg_pred) +
                                    (size_t)b * NV_ + (size_t)chunk * CHUNK_;

    int   cnt  = 0;
    float ssum = 0.f;

    // 5 (float4, int4) pairs; k<4 bounds are compile-time true (1024<1250),
    // only k=4 is predicated. Reg cap lets ptxas choose pipeline depth.
    float4 x[5]; int4 s[5];
    #pragma unroll
    for (int k = 0; k < 5; k++) {
        int i = threadIdx.x + k * 256;
        if (k < 4 || i < CHUNK_) { x[k] = __ldcs(&ml[i]); s[k] = __ldg(&sp[i]); }
    }
    #pragma unroll
    for (int k = 0; k < 5; k++) {
        int i = threadIdx.x + k * 256;
        if (k == 4 && i >= CHUNK_) continue;
        bool s0 = (x[k].x > 0.f) & (s[k].x == cls);
        bool s1 = (x[k].y > 0.f) & (s[k].y == cls);
        bool s2 = (x[k].z > 0.f) & (s[k].z == cls);
        bool s3 = (x[k].w > 0.f) & (s[k].w == cls);
        float4 o;
        o.x = s0 ? 1.f : 0.f;
        o.y = s1 ? 1.f : 0.f;
        o.z = s2 ? 1.f : 0.f;
        o.w = s3 ? 1.f : 0.f;
        __stcs(&om[i], o);
        cnt += (int)s0 + (int)s1 + (int)s2 + (int)s3;
        if (s0 | s1 | s2 | s3) {
            if (s0) ssum += __fdividef(1.f, 1.f + __expf(-x[k].x));
            if (s1) ssum += __fdividef(1.f, 1.f + __expf(-x[k].y));
            if (s2) ssum += __fdividef(1.f, 1.f + __expf(-x[k].z));
            if (s3) ssum += __fdividef(1.f, 1.f + __expf(-x[k].w));
        }
    }

    // Block reduction (8 warps); fixed shuffle-tree order -> deterministic.
    __shared__ int   scnt[8];
    __shared__ float ssh[8];
    #pragma unroll
    for (int off = 16; off > 0; off >>= 1) {
        cnt  += __shfl_down_sync(0xFFFFFFFFu, cnt,  off);
        ssum += __shfl_down_sync(0xFFFFFFFFu, ssum, off);
    }
    int wid  = threadIdx.x >> 5;
    int lane = threadIdx.x & 31;
    if (lane == 0) { scnt[wid] = cnt; ssh[wid] = ssum; }
    __syncthreads();
    if (threadIdx.x == 0) {
        int tc = 0; float ts = 0.f;
        #pragma unroll
        for (int w = 0; w < 8; w++) { tc += scnt[w]; ts += ssh[w]; }
        g_part_cnt[bq][chunk] = tc;     // plain store, no reset needed
        g_part_sum[bq][chunk] = ts;
    }
}

// ---------------------------------------------------------------------------
// Kernel 2 (tiny epilogue): grid 2 x 256 threads, one thread per row.
// Sum the 10 partials in fixed order (deterministic), argmax, write
// score/valid/cls. Flags to smem; the block then cooperatively zeroes any
// flagged row (instance class but cnt<50 -- with this data distribution
// cnt~1250, 34 sigma above threshold: a never-executed safety net).
// ---------------------------------------------------------------------------
__global__ __launch_bounds__(256)
void finalize_kernel(const float* __restrict__ cls_logits,
                     float* __restrict__ out_masks,
                     float* __restrict__ out_scores,
                     float* __restrict__ out_valid,
                     float* __restrict__ out_cls)
{
    __shared__ unsigned char sflag[256];
    const int bq = blockIdx.x * 256 + threadIdx.x;   // 0..511

    int   cnt = 0;
    float sum = 0.f;
    #pragma unroll
    for (int c = 0; c < S_; c++) {
        cnt += g_part_cnt[bq][c];
        sum += g_part_sum[bq][c];
    }
    const int cls = row_argmax(cls_logits + bq * C_);
    const int v   = (cnt >= MIN_PTS_NUM) && (cls >= MIN_INST_CLS);
    out_cls[bq]    = (float)cls;
    out_valid[bq]  = (float)v;
    out_scores[bq] = v ? sum / (float)cnt : 0.f;
    sflag[threadIdx.x] = (unsigned char)((!v) && (cls >= MIN_INST_CLS));
    __syncthreads();

    // Rare/never path: cooperative zero of flagged rows.
    for (int r = 0; r < 256; r++) {
        if (!sflag[r]) continue;
        int row = blockIdx.x * 256 + r;
        float4* __restrict__ om = reinterpret_cast<float4*>(out_masks) + (size_t)row * NV_;
        const float4 z = make_float4(0.f, 0.f, 0.f, 0.f);
        for (int i = threadIdx.x; i < NV_; i += 256)
            __stcs(&om[i], z);
    }
}

// ---------------------------------------------------------------------------
extern "C" void kernel_launch(void* const* d_in, const int* in_sizes, int n_in,
                              void* d_out, int out_size)
{
    const float* mask_logits = (const float*)d_in[0];   // [B,Q,N]  fp32
    const float* cls_logits  = (const float*)d_in[1];   // [B,Q,C]  fp32
    const int*   seg_pred    = (const int*)d_in[2];     // [B,N]    int32
    const int*   fg_idxs     = (const int*)d_in[3];     // [B*N]    int32
    float* out = (float*)d_out;

    float* out_masks  = out;
    float* out_scores = out + OFF_SCORES;
    float* out_valid  = out + OFF_VALID;
    float* out_cls    = out + OFF_CLS;
    float* out_gid    = out + OFF_GID;

    dim3 grid2(S_, BQ_);
    mask_chunk_kernel<<<grid2, 256>>>(mask_logits, cls_logits, seg_pred,
                                      fg_idxs, out_masks, out_gid);
    finalize_kernel<<<2, 256>>>(cls_logits, out_masks, out_scores,
                                out_valid, out_cls);
}

// round 10
// speedup vs baseline: 1.2645x; 1.2645x over previous
#include <cuda_runtime.h>

// Problem shapes (fixed for this dataset entry)
#define B_   4
#define Q_   128
#define N_   50000
#define C_   20
#define BQ_  (B_ * Q_)          // 512
#define BN_  (B_ * N_)          // 200000
#define NV_  (N_ / 4)           // 12500 float4 per row
#define S_   10                 // chunks per row
#define CHUNK_ (NV_ / S_)       // 1250 float4 per chunk
#define GIDV_ (BN_ / 4)         // 50000 int4 for gid convert
#define GID_PER_BLK ((GIDV_ + BQ_ - 1) / BQ_)    // 98 int4 per finalize block

#define MIN_PTS_NUM  50
#define MIN_INST_CLS 4

// Output layout (fp32 concatenation, matching reference return order)
#define OFF_SCORES ((size_t)BQ_ * N_)            // 25,600,000
#define OFF_VALID  (OFF_SCORES + BQ_)
#define OFF_CLS    (OFF_VALID + BQ_)
#define OFF_GID    (OFF_CLS + BQ_)

// Scratch (no device allocation -> __device__ globals). Written by plain
// overwriting stores every invocation -> idempotent across graph replays,
// no reset, no atomics, no fences.
__device__ int   g_part_cnt[BQ_][S_];
__device__ float g_part_sum[BQ_][S_];

// Inline per-row argmax over C=20 class logits. Matches jnp.argmax first-max.
__device__ __forceinline__ int row_argmax(const float* __restrict__ p)
{
    float best = __ldg(&p[0]);
    int bi = 0;
    #pragma unroll
    for (int c = 1; c < C_; c++) {
        float v = __ldg(&p[c]);
        if (v > best) { best = v; bi = c; }
    }
    return bi;
}

// ---------------------------------------------------------------------------
// Kernel 1: grid (S_, BQ_). One block per 1250-float4 chunk of one (b,q) row.
// __launch_bounds__(256, 6): keeps regs <= 40 -> 6 blocks/SM (occ ~66-75%).
// cls<4 rows are invalid regardless of count -> stream zeros, no logit read.
// Otherwise: sel = (logit>0) & (seg==cls)  [sigmoid(x)>0.5 <=> x>0 -> no
// MUFU for selection]; write mask (streaming), block-reduce (count, sigmoid
// sum over selected), plain-store partials into the per-(row,chunk) slot.
// ---------------------------------------------------------------------------
__global__ __launch_bounds__(256, 6)
void mask_chunk_kernel(const float* __restrict__ mask_logits,
                       const float* __restrict__ cls_logits,
                       const int* __restrict__ seg_pred,
                       float* __restrict__ out_masks)
{
    const int chunk = blockIdx.x;
    const int bq    = blockIdx.y;
    const int b     = bq >> 7;            // / Q_
    const int cls   = row_argmax(cls_logits + bq * C_);
    const size_t base = (size_t)bq * NV_ + (size_t)chunk * CHUNK_;

    float4* __restrict__ om = reinterpret_cast<float4*>(out_masks) + base;

    if (cls < MIN_INST_CLS) {
        const float4 z = make_float4(0.f, 0.f, 0.f, 0.f);
        #pragma unroll
        for (int k = 0; k < 5; k++) {
            int i = threadIdx.x + k * 256;
            if (i < CHUNK_) __stcs(&om[i], z);
        }
        if (threadIdx.x == 0) {           // still publish partials (zero)
            g_part_cnt[bq][chunk] = 0;
            g_part_sum[bq][chunk] = 0.f;
        }
        return;
    }

    const float4* __restrict__ ml = reinterpret_cast<const float4*>(mask_logits) + base;
    const int4*   __restrict__ sp = reinterpret_cast<const int4*>(seg_pred) +
                                    (size_t)b * NV_ + (size_t)chunk * CHUNK_;

    int   cnt  = 0;
    float ssum = 0.f;

    // 5 (float4, int4) pairs; k<4 bounds are compile-time true (1024<1250),
    // only k=4 is predicated. Reg cap lets ptxas choose pipeline depth.
    float4 x[5]; int4 s[5];
    #pragma unroll
    for (int k = 0; k < 5; k++) {
        int i = threadIdx.x + k * 256;
        if (k < 4 || i < CHUNK_) { x[k] = __ldcs(&ml[i]); s[k] = __ldg(&sp[i]); }
    }
    #pragma unroll
    for (int k = 0; k < 5; k++) {
        int i = threadIdx.x + k * 256;
        if (k == 4 && i >= CHUNK_) continue;
        bool s0 = (x[k].x > 0.f) & (s[k].x == cls);
        bool s1 = (x[k].y > 0.f) & (s[k].y == cls);
        bool s2 = (x[k].z > 0.f) & (s[k].z == cls);
        bool s3 = (x[k].w > 0.f) & (s[k].w == cls);
        float4 o;
        o.x = s0 ? 1.f : 0.f;
        o.y = s1 ? 1.f : 0.f;
        o.z = s2 ? 1.f : 0.f;
        o.w = s3 ? 1.f : 0.f;
        __stcs(&om[i], o);
        cnt += (int)s0 + (int)s1 + (int)s2 + (int)s3;
        if (s0 | s1 | s2 | s3) {
            if (s0) ssum += __fdividef(1.f, 1.f + __expf(-x[k].x));
            if (s1) ssum += __fdividef(1.f, 1.f + __expf(-x[k].y));
            if (s2) ssum += __fdividef(1.f, 1.f + __expf(-x[k].z));
            if (s3) ssum += __fdividef(1.f, 1.f + __expf(-x[k].w));
        }
    }

    // Block reduction (8 warps); fixed shuffle-tree order -> deterministic.
    __shared__ int   scnt[8];
    __shared__ float ssh[8];
    #pragma unroll
    for (int off = 16; off > 0; off >>= 1) {
        cnt  += __shfl_down_sync(0xFFFFFFFFu, cnt,  off);
        ssum += __shfl_down_sync(0xFFFFFFFFu, ssum, off);
    }
    int wid  = threadIdx.x >> 5;
    int lane = threadIdx.x & 31;
    if (lane == 0) { scnt[wid] = cnt; ssh[wid] = ssum; }
    __syncthreads();
    if (threadIdx.x == 0) {
        int tc = 0; float ts = 0.f;
        #pragma unroll
        for (int w = 0; w < 8; w++) { tc += scnt[w]; ts += ssh[w]; }
        g_part_cnt[bq][chunk] = tc;     // plain store, no reset needed
        g_part_sum[bq][chunk] = ts;
    }
}

// ---------------------------------------------------------------------------
// Kernel 2 (epilogue): 512 blocks, one per row bq = blockIdx.x.
//  - gid convert, vectorized int4 -> float4: threads 0..97 of each block
//    handle one int4 each (4x fewer transactions than R8's scalar version,
//    full 512-block parallelism).
//  - thread 0: sums the 10 partials in fixed order (deterministic), argmax,
//    writes score/valid/cls, raises smem flag if the row needs re-zero
//    (instance class but cnt<50; with this data cnt~1250 -- never taken).
//  - whole block zeroes the row iff flagged (safety net).
// ---------------------------------------------------------------------------
__global__ __launch_bounds__(256)
void finalize_kernel(const float* __restrict__ cls_logits,
                     const int* __restrict__ fg_idxs,
                     float* __restrict__ out_masks,
                     float* __restrict__ out_scores,
                     float* __restrict__ out_valid,
                     float* __restrict__ out_cls,
                     float* __restrict__ out_gid)
{
    const int bq = blockIdx.x;

    // Vectorized gid convert
    {
        int vi = bq * GID_PER_BLK + threadIdx.x;
        if (threadIdx.x < GID_PER_BLK && vi < GIDV_) {
            int4 v = __ldg(&reinterpret_cast<const int4*>(fg_idxs)[vi]);
            float4 f;
            f.x = (float)v.x; f.y = (float)v.y;
            f.z = (float)v.z; f.w = (float)v.w;
            reinterpret_cast<float4*>(out_gid)[vi] = f;
        }
    }

    __shared__ int flag;
    if (threadIdx.x == 0) {
        int   cnt = 0;
        float sum = 0.f;
        #pragma unroll
        for (int c = 0; c < S_; c++) {
            cnt += g_part_cnt[bq][c];
            sum += g_part_sum[bq][c];
        }
        const int cls = row_argmax(cls_logits + bq * C_);
        const int v   = (cnt >= MIN_PTS_NUM) && (cls >= MIN_INST_CLS);
        out_cls[bq]    = (float)cls;
        out_valid[bq]  = (float)v;
        out_scores[bq] = v ? sum / (float)cnt : 0.f;
        flag = (!v) && (cls >= MIN_INST_CLS);
    }
    __syncthreads();

    if (flag) {                            // rare/never: slow path is fine
        float4* __restrict__ om = reinterpret_cast<float4*>(out_masks) + (size_t)bq * NV_;
        const float4 z = make_float4(0.f, 0.f, 0.f, 0.f);
        for (int i = threadIdx.x; i < NV_; i += 256)
            __stcs(&om[i], z);
    }
}

// ---------------------------------------------------------------------------
extern "C" void kernel_launch(void* const* d_in, const int* in_sizes, int n_in,
                              void* d_out, int out_size)
{
    const float* mask_logits = (const float*)d_in[0];   // [B,Q,N]  fp32
    const float* cls_logits  = (const float*)d_in[1];   // [B,Q,C]  fp32
    const int*   seg_pred    = (const int*)d_in[2];     // [B,N]    int32
    const int*   fg_idxs     = (const int*)d_in[3];     // [B*N]    int32
    float* out = (float*)d_out;

    float* out_masks  = out;
    float* out_scores = out + OFF_SCORES;
    float* out_valid  = out + OFF_VALID;
    float* out_cls    = out + OFF_CLS;
    float* out_gid    = out + OFF_GID;

    dim3 grid2(S_, BQ_);
    mask_chunk_kernel<<<grid2, 256>>>(mask_logits, cls_logits, seg_pred,
                                      out_masks);
    finalize_kernel<<<BQ_, 256>>>(cls_logits, fg_idxs, out_masks,
                                  out_scores, out_valid, out_cls, out_gid);
}